// round 5
// baseline (speedup 1.0000x reference)
#include <cuda_runtime.h>
#include <cuda_fp16.h>

// ---------------- problem constants ----------------
#define N1V   131072
#define N2V   2368
#define E1V   2097152
#define E2V   37888
#define ROIS  148
#define BSZV  16
#define HIDV  64
#define EMBV  (ROIS * HIDV)      // 9472
#define NSEG  (BSZV * ROIS)      // 2368
#define NKS   64
#define KSLICE 148               // 9472 / 64
#define BN_EPSV 1e-5f
#define LRELU  0.01f

#define NB1 512                  // N1V / 256
#define NB2 10                   // ceil(N2V / 256)
#define GB1 512                  // gemm blocks graph1 (256 rows each)
#define GB2 10

struct __align__(8) EP { int s; float w; };

// ---------------- scratch (device globals; no runtime alloc) ----------------
__device__ __align__(16) __half2 g_bufH1[(size_t)N1V * 32];   // gather input (fp16)
__device__ __align__(16) float   g_bufY1[(size_t)N1V * 64];   // gatherA output (fp32)
__device__ float g_deg1[N1V];
__device__ int   g_cnti1[N1V];
__device__ int   g_rowptr1[N1V + 1];
__device__ int   g_cursor1[N1V];
__device__ int   g_bsum1[512];
__device__ EP    g_pay1[E1V];

__device__ __align__(16) __half2 g_bufH2[(size_t)N2V * 32];
__device__ __align__(16) float   g_bufY2[(size_t)N2V * 64];
__device__ float g_deg2[N2V];
__device__ int   g_cnti2[N2V];
__device__ int   g_rowptr2[N2V + 1];
__device__ int   g_cursor2[N2V];
__device__ int   g_bsum2[512];
__device__ EP    g_pay2[E2V];

__device__ __align__(16) float g_pool1[NSEG * 64];
__device__ float g_cntf1[NSEG];
__device__ __align__(16) float g_pool2[NSEG * 64];
__device__ float g_cntf2[NSEG];

__device__ __align__(16) float g_s[BSZV * EMBV];
__device__ float g_part[NKS * BSZV * 1000];
__device__ float g_hidden[BSZV * 1000];

// ---------------- setup kernels ----------------
__global__ void init_kernel() {
    int idx = blockIdx.x * 256 + threadIdx.x;
    if (idx < N1V) { g_deg1[idx] = 1.0f; g_cnti1[idx] = 0; }
    if (idx < N2V) { g_deg2[idx] = 1.0f; g_cnti2[idx] = 0; }
    if (idx < NSEG * 64) { g_pool1[idx] = 0.0f; g_pool2[idx] = 0.0f; }
    if (idx < NSEG)      { g_cntf1[idx] = 0.0f; g_cntf2[idx] = 0.0f; }
}

__global__ void hist_all(const int* __restrict__ dst1, const float* __restrict__ ew1,
                         const int* __restrict__ dst2, const float* __restrict__ ew2) {
    int e = blockIdx.x * 256 + threadIdx.x;
    if (e < E1V) {
        int d = dst1[e];
        atomicAdd(&g_cnti1[d], 1);
        atomicAdd(&g_deg1[d], ew1[e]);
    } else if (e < E1V + E2V) {
        int e2 = e - E1V;
        int d = dst2[e2];
        atomicAdd(&g_cnti2[d], 1);
        atomicAdd(&g_deg2[d], ew2[e2]);
    }
}

__global__ void rsqrt_all() {
    int i = blockIdx.x * 256 + threadIdx.x;
    if (i < N1V) g_deg1[i] = rsqrtf(g_deg1[i]);
    else if (i < N1V + N2V) g_deg2[i - N1V] = rsqrtf(g_deg2[i - N1V]);
}

__global__ void scan_block_all() {
    __shared__ int sm[256];
    int gb = blockIdx.x;
    const int* cnt; int* excl; int* bsum; int n; int lb;
    if (gb < NB1) { cnt = g_cnti1; excl = g_rowptr1; bsum = g_bsum1; n = N1V; lb = gb; }
    else          { cnt = g_cnti2; excl = g_rowptr2; bsum = g_bsum2; n = N2V; lb = gb - NB1; }
    int i = lb * 256 + threadIdx.x;
    int v = (i < n) ? cnt[i] : 0;
    sm[threadIdx.x] = v; __syncthreads();
#pragma unroll
    for (int off = 1; off < 256; off <<= 1) {
        int t = (threadIdx.x >= off) ? sm[threadIdx.x - off] : 0;
        __syncthreads();
        sm[threadIdx.x] += t;
        __syncthreads();
    }
    if (i < n) excl[i] = sm[threadIdx.x] - v;
    if (threadIdx.x == 255) bsum[lb] = sm[255];
}

__global__ void scan_bsum_all() {
    __shared__ int sm[512];
    int* bsum = (blockIdx.x == 0) ? g_bsum1 : g_bsum2;
    int nb    = (blockIdx.x == 0) ? NB1 : NB2;
    int v = (threadIdx.x < nb) ? bsum[threadIdx.x] : 0;
    sm[threadIdx.x] = v; __syncthreads();
#pragma unroll
    for (int off = 1; off < 512; off <<= 1) {
        int t = (threadIdx.x >= off) ? sm[threadIdx.x - off] : 0;
        __syncthreads();
        sm[threadIdx.x] += t;
        __syncthreads();
    }
    if (threadIdx.x < nb) bsum[threadIdx.x] = sm[threadIdx.x] - v;
}

__global__ void scan_add_all() {
    int gb = blockIdx.x;
    int* rowptr; int* cursor; const int* bsum; int n; int E; int lb;
    if (gb < NB1) { rowptr = g_rowptr1; cursor = g_cursor1; bsum = g_bsum1; n = N1V; E = E1V; lb = gb; }
    else          { rowptr = g_rowptr2; cursor = g_cursor2; bsum = g_bsum2; n = N2V; E = E2V; lb = gb - NB1; }
    int i = lb * 256 + threadIdx.x;
    if (i < n) {
        int r = rowptr[i] + bsum[i >> 8];
        rowptr[i] = r;
        cursor[i] = r;
    }
    if (i == 0) rowptr[n] = E;
}

__global__ void csr_all(const int* __restrict__ src1, const int* __restrict__ dst1,
                        const float* __restrict__ ew1,
                        const int* __restrict__ src2, const int* __restrict__ dst2,
                        const float* __restrict__ ew2) {
    int e = blockIdx.x * 256 + threadIdx.x;
    if (e < E1V) {
        int s = src1[e], d = dst1[e];
        EP p; p.s = s; p.w = g_deg1[s] * ew1[e] * g_deg1[d];
        int pos = atomicAdd(&g_cursor1[d], 1);
        g_pay1[pos] = p;
    } else if (e < E1V + E2V) {
        int e2 = e - E1V;
        int s = src2[e2], d = dst2[e2];
        EP p; p.s = s; p.w = g_deg2[s] * ew2[e2] * g_deg2[d];
        int pos = atomicAdd(&g_cursor2[d], 1);
        g_pay2[pos] = p;
    }
}

// ---------------- GEMM body: outH(n,64 fp16) = A(n,K fp32) @ Ws(K,64) ----
// Tiling: 4 rows x 16 cols per thread; 256 threads -> 256 rows/block.
// acc = 32 f32x2 (64 regs), launch_bounds caps regs at 128 -> 2 blocks/SM (16 warps).
template<int K>
__device__ __forceinline__ void gemm_body(const float* __restrict__ A,
                                          const float* __restrict__ Wg,
                                          __half2* __restrict__ outH, int n, int lb) {
    __shared__ float Ws[K * 64];
    for (int i = threadIdx.x; i < K * 64; i += 256) Ws[i] = Wg[i];
    __syncthreads();
    int colg = threadIdx.x & 3;          // 16-col group: cols [colg*16, colg*16+16)
    int rowg = threadIdx.x >> 2;         // 0..63
    int r0 = lb * 256 + rowg * 4;
    if (r0 >= n) return;
    int nr = n - r0; if (nr > 4) nr = 4;

    double acc[4][8];
#pragma unroll
    for (int r = 0; r < 4; r++)
#pragma unroll
        for (int j = 0; j < 8; j++) acc[r][j] = 0.0;

    const float* a0 = A + (size_t)r0 * K;
#pragma unroll 1
    for (int k4 = 0; k4 < K / 4; k4++) {
        float4 av[4];
#pragma unroll
        for (int r = 0; r < 4; r++)
            av[r] = (r < nr) ? reinterpret_cast<const float4*>(a0 + (size_t)r * K)[k4]
                             : make_float4(0.f, 0.f, 0.f, 0.f);
#pragma unroll
        for (int kk = 0; kk < 4; kk++) {
            const double* w = reinterpret_cast<const double*>(
                &Ws[(k4 * 4 + kk) * 64 + colg * 16]);
            double wv[8];
#pragma unroll
            for (int j = 0; j < 8; j++) wv[j] = w[j];
#pragma unroll
            for (int r = 0; r < 4; r++) {
                float a = (&av[r].x)[kk];
                double ap;
                asm("mov.b64 %0, {%1,%1};" : "=d"(ap) : "f"(a));
#pragma unroll
                for (int j = 0; j < 8; j++)
                    asm("fma.rn.f32x2 %0, %1, %2, %0;"
                        : "+d"(acc[r][j]) : "d"(wv[j]), "d"(ap));
            }
        }
    }
#pragma unroll
    for (int r = 0; r < 4; r++) {
        if (r >= nr) break;
        __half2 t[8];
#pragma unroll
        for (int j = 0; j < 8; j++) {
            float lo, hi;
            asm("mov.b64 {%0,%1}, %2;" : "=f"(lo), "=f"(hi) : "d"(acc[r][j]));
            t[j] = __floats2half2_rn(lo, hi);
        }
        uint4* o = reinterpret_cast<uint4*>(outH + (size_t)(r0 + r) * 32 + colg * 8);
        const uint4* ts = reinterpret_cast<const uint4*>(t);
        o[0] = ts[0];
        o[1] = ts[1];
    }
}

template<int K>
__global__ void __launch_bounds__(256, 2) gemm_all(const float* __restrict__ A1,
                                                   const float* __restrict__ W1,
                                                   __half2* __restrict__ o1,
                                                   const float* __restrict__ A2,
                                                   const float* __restrict__ W2,
                                                   __half2* __restrict__ o2) {
    int gb = blockIdx.x;
    if (gb < GB1) gemm_body<K>(A1, W1, o1, N1V, gb);
    else          gemm_body<K>(A2, W2, o2, N2V, gb - GB1);
}

// ---------------- fused gather: relu(sum nrm*h[src] + h/deg + bias); fp16 in, fp32 acc ----
template<bool POOL>
__global__ void gather_all(const __half2* __restrict__ h1, const float* __restrict__ bias1,
                           float* __restrict__ out1,
                           const __half2* __restrict__ h2g, const float* __restrict__ bias2,
                           float* __restrict__ out2,
                           const int* __restrict__ roi1, const int* __restrict__ bat1,
                           const int* __restrict__ roi2, const int* __restrict__ bat2) {
    int w = (blockIdx.x * blockDim.x + threadIdx.x) >> 5;
    int lane = threadIdx.x & 31;
    const EP* pay; const int* rowptr; const __half2* hh; const float* dinv; const float* bias;
    float* out; const int* roi; const int* bat; float* pool; float* cntf;
    int node;
    if (w < N1V) {
        node = w; pay = g_pay1; rowptr = g_rowptr1; hh = h1; dinv = g_deg1; bias = bias1;
        out = out1; roi = roi1; bat = bat1; pool = g_pool1; cntf = g_cntf1;
    } else if (w < N1V + N2V) {
        node = w - N1V; pay = g_pay2; rowptr = g_rowptr2; hh = h2g; dinv = g_deg2; bias = bias2;
        out = out2; roi = roi2; bat = bat2; pool = g_pool2; cntf = g_cntf2;
    } else return;

    int beg = rowptr[node], end = rowptr[node + 1];
    float di = dinv[node];
    float sl = di * di;
    float2 hv = __half22float2(hh[(size_t)node * 32 + lane]);
    float ax = hv.x * sl, ay = hv.y * sl;

    int e = beg;
    for (; e + 8 <= end; e += 8) {
        EP p[8];
#pragma unroll
        for (int i = 0; i < 8; i++) p[i] = pay[e + i];
        float2 v[8];
#pragma unroll
        for (int i = 0; i < 8; i++) v[i] = __half22float2(hh[(size_t)p[i].s * 32 + lane]);
#pragma unroll
        for (int i = 0; i < 8; i++) { ax += v[i].x * p[i].w; ay += v[i].y * p[i].w; }
    }
    for (; e < end; e++) {
        EP p = pay[e];
        float2 v = __half22float2(hh[(size_t)p.s * 32 + lane]);
        ax += v.x * p.w;
        ay += v.y * p.w;
    }
    float2 b2 = reinterpret_cast<const float2*>(bias)[lane];
    ax = fmaxf(ax + b2.x, 0.0f);
    ay = fmaxf(ay + b2.y, 0.0f);
    if (POOL) {
        int seg = bat[node] * ROIS + roi[node];
        float* p = pool + (size_t)seg * 64 + lane * 2;
        asm volatile("red.global.add.v2.f32 [%0], {%1,%2};"
                     :: "l"(p), "f"(ax), "f"(ay) : "memory");
        if (lane == 0) atomicAdd(&cntf[seg], 1.0f);
    } else {
        reinterpret_cast<float2*>(out)[(size_t)node * 32 + lane] = make_float2(ax, ay);
    }
}

// ---------------- pooling means + embeddings -> d_out ----------------
__global__ void pool_finalize(float* __restrict__ out) {
    int idx = blockIdx.x * 256 + threadIdx.x;
    if (idx >= NSEG * 64) return;
    int seg = idx >> 6;
    float e1 = g_pool1[idx] / fmaxf(g_cntf1[seg], 1.0f);
    float e2 = g_pool2[idx] / fmaxf(g_cntf2[seg], 1.0f);
    float sv = e1 + e2;
    out[32 + idx] = e1;
    out[32 + BSZV * EMBV + idx] = e2;
    out[32 + 2 * BSZV * EMBV + idx] = sv;
    g_s[idx] = sv;
}

// ---------------- classifier ----------------
__global__ void mlp1_partial(const float* __restrict__ Wm1) {
    __shared__ float sm[BSZV * KSLICE];   // 9.5 KB
    int ks = blockIdx.y;
    int k0 = ks * KSLICE;
    for (int i = threadIdx.x; i < BSZV * KSLICE; i += blockDim.x) {
        int b = i / KSLICE, kk = i - b * KSLICE;
        sm[i] = g_s[b * EMBV + k0 + kk];
    }
    __syncthreads();
    int j = blockIdx.x * 128 + threadIdx.x;
    if (j >= 1000) return;
    float acc[BSZV];
#pragma unroll
    for (int b = 0; b < BSZV; b++) acc[b] = 0.0f;
#pragma unroll 1
    for (int kk = 0; kk < KSLICE; kk += 4) {
        float w0 = Wm1[(size_t)(k0 + kk) * 1000 + j];
        float w1 = Wm1[(size_t)(k0 + kk + 1) * 1000 + j];
        float w2 = Wm1[(size_t)(k0 + kk + 2) * 1000 + j];
        float w3 = Wm1[(size_t)(k0 + kk + 3) * 1000 + j];
#pragma unroll
        for (int b = 0; b < BSZV; b++) {
            float4 sv = *reinterpret_cast<const float4*>(&sm[b * KSLICE + kk]);
            acc[b] += sv.x * w0 + sv.y * w1 + sv.z * w2 + sv.w * w3;
        }
    }
#pragma unroll
    for (int b = 0; b < BSZV; b++) g_part[((size_t)ks * BSZV + b) * 1000 + j] = acc[b];
}

__global__ void mlp1_reduce(const float* __restrict__ bm1, const float* __restrict__ gamma,
                            const float* __restrict__ beta, const float* __restrict__ mean,
                            const float* __restrict__ var) {
    int idx = blockIdx.x * 256 + threadIdx.x;
    if (idx >= BSZV * 1000) return;
    int b = idx / 1000, j = idx - b * 1000;
    float v = bm1[j];
#pragma unroll 8
    for (int ks = 0; ks < NKS; ks++) v += g_part[((size_t)ks * BSZV + b) * 1000 + j];
    float sc = gamma[j] * rsqrtf(var[j] + BN_EPSV);
    v = (v - mean[j]) * sc + beta[j];
    g_hidden[idx] = v > 0.0f ? v : LRELU * v;
}

__global__ void mlp2_kernel(const float* __restrict__ Wm2, const float* __restrict__ bm2,
                            float* __restrict__ out) {
    int w = threadIdx.x >> 5, lane = threadIdx.x & 31;
    int b = w >> 1, o = w & 1;
    float acc = 0.0f;
    for (int k = lane; k < 1000; k += 32) acc += g_hidden[b * 1000 + k] * Wm2[k * 2 + o];
#pragma unroll
    for (int off = 16; off; off >>= 1) acc += __shfl_down_sync(0xffffffffu, acc, off);
    if (lane == 0) out[b * 2 + o] = acc + bm2[o];
}

// ---------------- launcher ----------------
extern "C" void kernel_launch(void* const* d_in, const int* in_sizes, int n_in,
                              void* d_out, int out_size) {
    const float* x1   = (const float*)d_in[0];
    const int*   nlab = (const int*)  d_in[1];
    const int*   ei1  = (const int*)  d_in[2];
    const float* ew1  = (const float*)d_in[3];
    const int*   bat1 = (const int*)  d_in[4];
    const float* x2   = (const float*)d_in[5];
    const int*   rlab = (const int*)  d_in[6];
    const int*   ei2  = (const int*)  d_in[7];
    const float* ew2  = (const float*)d_in[8];
    const int*   bat2 = (const int*)  d_in[9];
    const float* W1a = (const float*)d_in[10]; const float* b1a = (const float*)d_in[11];
    const float* W1b = (const float*)d_in[12]; const float* b1b = (const float*)d_in[13];
    const float* W2a = (const float*)d_in[14]; const float* b2a = (const float*)d_in[15];
    const float* W2b = (const float*)d_in[16]; const float* b2b = (const float*)d_in[17];
    const float* Wm1 = (const float*)d_in[18]; const float* bm1 = (const float*)d_in[19];
    const float* gam = (const float*)d_in[20]; const float* bet = (const float*)d_in[21];
    const float* bmn = (const float*)d_in[22]; const float* bvr = (const float*)d_in[23];
    const float* Wm2 = (const float*)d_in[24]; const float* bm2 = (const float*)d_in[25];

    const int* src1 = ei1;          const int* dst1 = ei1 + E1V;
    const int* src2 = ei2;          const int* dst2 = ei2 + E2V;

    __half2 *bufH1, *bufH2;
    float *bufY1, *bufY2;
    cudaGetSymbolAddress((void**)&bufH1, g_bufH1);
    cudaGetSymbolAddress((void**)&bufY1, g_bufY1);
    cudaGetSymbolAddress((void**)&bufH2, g_bufH2);
    cudaGetSymbolAddress((void**)&bufY2, g_bufY2);

    float* out = (float*)d_out;
    auto cdiv = [](long long a, long long b) { return (int)((a + b - 1) / b); };

    // structure build + layer-A GEMM (gemm kept 4th: ncu samples launch #4)
    init_kernel<<<cdiv(NSEG * 64, 256), 256>>>();
    hist_all<<<cdiv(E1V + E2V, 256), 256>>>(dst1, ew1, dst2, ew2);
    rsqrt_all<<<cdiv(N1V + N2V, 256), 256>>>();
    gemm_all<128><<<GB1 + GB2, 256>>>(x1, W1a, bufH1, x2, W2a, bufH2);
    scan_block_all<<<NB1 + NB2, 256>>>();
    scan_bsum_all<<<2, 512>>>();
    scan_add_all<<<NB1 + NB2, 256>>>();
    csr_all<<<cdiv(E1V + E2V, 256), 256>>>(src1, dst1, ew1, src2, dst2, ew2);
    // layer-A aggregate + bias + relu (fp32 out for gemmB)
    gather_all<false><<<cdiv((long long)(N1V + N2V) * 32, 256), 256>>>(
        bufH1, b1a, bufY1, bufH2, b2a, bufY2, nullptr, nullptr, nullptr, nullptr);
    // layer-B GEMM (fp32 in, fp16 out)
    gemm_all<64><<<GB1 + GB2, 256>>>(bufY1, W1b, bufH1, bufY2, W2b, bufH2);
    // layer-B aggregate + bias + relu + ROI pooling
    gather_all<true><<<cdiv((long long)(N1V + N2V) * 32, 256), 256>>>(
        bufH1, b1b, nullptr, bufH2, b2b, nullptr, nlab, bat1, rlab, bat2);
    // pooled means + embeddings -> d_out
    pool_finalize<<<cdiv(NSEG * 64, 256), 256>>>(out);
    // classifier
    mlp1_partial<<<dim3(8, NKS), 128>>>(Wm1);
    mlp1_reduce<<<cdiv(BSZV * 1000, 256), 256>>>(bm1, gam, bet, bmn, bvr);
    mlp2_kernel<<<1, 1024>>>(Wm2, bm2, out);
}

// round 6
// speedup vs baseline: 1.0454x; 1.0454x over previous
#include <cuda_runtime.h>
#include <cuda_fp16.h>

// ---------------- problem constants ----------------
#define N1V   131072
#define N2V   2368
#define E1V   2097152
#define E2V   37888
#define ROIS  148
#define BSZV  16
#define HIDV  64
#define EMBV  (ROIS * HIDV)      // 9472
#define NSEG  (BSZV * ROIS)      // 2368
#define NKS   64
#define KSLICE 148               // 9472 / 64
#define BN_EPSV 1e-5f
#define LRELU  0.01f

#define NB1 512                  // N1V / 256
#define NB2 10                   // ceil(N2V / 256)
#define GB1 1024                 // gemm blocks graph1 (128 rows each)
#define GB2 19                   // ceil(N2V / 128)

struct __align__(8) EP { int s; float w; };

// ---------------- scratch (device globals; no runtime alloc) ----------------
__device__ __align__(16) __half2 g_bufH1[(size_t)N1V * 32];   // gather input (fp16)
__device__ __align__(16) float   g_bufY1[(size_t)N1V * 64];   // gatherA output (fp32)
__device__ float g_deg1[N1V];
__device__ int   g_cnti1[N1V];
__device__ int   g_rowptr1[N1V + 1];
__device__ int   g_cursor1[N1V];
__device__ int   g_bsum1[512];
__device__ EP    g_pay1[E1V];

__device__ __align__(16) __half2 g_bufH2[(size_t)N2V * 32];
__device__ __align__(16) float   g_bufY2[(size_t)N2V * 64];
__device__ float g_deg2[N2V];
__device__ int   g_cnti2[N2V];
__device__ int   g_rowptr2[N2V + 1];
__device__ int   g_cursor2[N2V];
__device__ int   g_bsum2[512];
__device__ EP    g_pay2[E2V];

__device__ __align__(16) float g_pool1[NSEG * 64];
__device__ float g_cntf1[NSEG];
__device__ __align__(16) float g_pool2[NSEG * 64];
__device__ float g_cntf2[NSEG];

__device__ __align__(16) float g_s[BSZV * EMBV];
__device__ float g_part[NKS * BSZV * 1000];
__device__ float g_hidden[BSZV * 1000];

// ---------------- setup kernels ----------------
__global__ void init_kernel() {
    int idx = blockIdx.x * 256 + threadIdx.x;
    if (idx < N1V) { g_deg1[idx] = 1.0f; g_cnti1[idx] = 0; }
    if (idx < N2V) { g_deg2[idx] = 1.0f; g_cnti2[idx] = 0; }
    if (idx < NSEG * 64) { g_pool1[idx] = 0.0f; g_pool2[idx] = 0.0f; }
    if (idx < NSEG)      { g_cntf1[idx] = 0.0f; g_cntf2[idx] = 0.0f; }
}

__global__ void hist_all(const int* __restrict__ dst1, const float* __restrict__ ew1,
                         const int* __restrict__ dst2, const float* __restrict__ ew2) {
    int e = blockIdx.x * 256 + threadIdx.x;
    if (e < E1V) {
        int d = dst1[e];
        atomicAdd(&g_cnti1[d], 1);
        atomicAdd(&g_deg1[d], ew1[e]);
    } else if (e < E1V + E2V) {
        int e2 = e - E1V;
        int d = dst2[e2];
        atomicAdd(&g_cnti2[d], 1);
        atomicAdd(&g_deg2[d], ew2[e2]);
    }
}

__global__ void rsqrt_all() {
    int i = blockIdx.x * 256 + threadIdx.x;
    if (i < N1V) g_deg1[i] = rsqrtf(g_deg1[i]);
    else if (i < N1V + N2V) g_deg2[i - N1V] = rsqrtf(g_deg2[i - N1V]);
}

__global__ void scan_block_all() {
    __shared__ int sm[256];
    int gb = blockIdx.x;
    const int* cnt; int* excl; int* bsum; int n; int lb;
    if (gb < NB1) { cnt = g_cnti1; excl = g_rowptr1; bsum = g_bsum1; n = N1V; lb = gb; }
    else          { cnt = g_cnti2; excl = g_rowptr2; bsum = g_bsum2; n = N2V; lb = gb - NB1; }
    int i = lb * 256 + threadIdx.x;
    int v = (i < n) ? cnt[i] : 0;
    sm[threadIdx.x] = v; __syncthreads();
#pragma unroll
    for (int off = 1; off < 256; off <<= 1) {
        int t = (threadIdx.x >= off) ? sm[threadIdx.x - off] : 0;
        __syncthreads();
        sm[threadIdx.x] += t;
        __syncthreads();
    }
    if (i < n) excl[i] = sm[threadIdx.x] - v;
    if (threadIdx.x == 255) bsum[lb] = sm[255];
}

__global__ void scan_bsum_all() {
    __shared__ int sm[512];
    int* bsum = (blockIdx.x == 0) ? g_bsum1 : g_bsum2;
    int nb    = (blockIdx.x == 0) ? NB1 : NB2;
    int v = (threadIdx.x < nb) ? bsum[threadIdx.x] : 0;
    sm[threadIdx.x] = v; __syncthreads();
#pragma unroll
    for (int off = 1; off < 512; off <<= 1) {
        int t = (threadIdx.x >= off) ? sm[threadIdx.x - off] : 0;
        __syncthreads();
        sm[threadIdx.x] += t;
        __syncthreads();
    }
    if (threadIdx.x < nb) bsum[threadIdx.x] = sm[threadIdx.x] - v;
}

__global__ void scan_add_all() {
    int gb = blockIdx.x;
    int* rowptr; int* cursor; const int* bsum; int n; int E; int lb;
    if (gb < NB1) { rowptr = g_rowptr1; cursor = g_cursor1; bsum = g_bsum1; n = N1V; E = E1V; lb = gb; }
    else          { rowptr = g_rowptr2; cursor = g_cursor2; bsum = g_bsum2; n = N2V; E = E2V; lb = gb - NB1; }
    int i = lb * 256 + threadIdx.x;
    if (i < n) {
        int r = rowptr[i] + bsum[i >> 8];
        rowptr[i] = r;
        cursor[i] = r;
    }
    if (i == 0) rowptr[n] = E;
}

__global__ void csr_all(const int* __restrict__ src1, const int* __restrict__ dst1,
                        const float* __restrict__ ew1,
                        const int* __restrict__ src2, const int* __restrict__ dst2,
                        const float* __restrict__ ew2) {
    int e = blockIdx.x * 256 + threadIdx.x;
    if (e < E1V) {
        int s = src1[e], d = dst1[e];
        EP p; p.s = s; p.w = g_deg1[s] * ew1[e] * g_deg1[d];
        int pos = atomicAdd(&g_cursor1[d], 1);
        g_pay1[pos] = p;
    } else if (e < E1V + E2V) {
        int e2 = e - E1V;
        int s = src2[e2], d = dst2[e2];
        EP p; p.s = s; p.w = g_deg2[s] * ew2[e2] * g_deg2[d];
        int pos = atomicAdd(&g_cursor2[d], 1);
        g_pay2[pos] = p;
    }
}

// ---------------- GEMM body: outH(n,64 fp16) = A(n,K fp32) @ Ws(K,64) ----
// Tiling: 2 rows x 32 cols per thread; 128 threads -> 128 rows/block.
// W slice per k-step via 8x LDS.128 (double2), reused across both rows.
// acc = 32 f32x2 (64 regs) + W 32 regs -> ~110 regs; 3 blocks/SM = 12 warps.
template<int K>
__device__ __forceinline__ void gemm_body(const float* __restrict__ A,
                                          const float* __restrict__ Wg,
                                          __half2* __restrict__ outH, int n, int lb) {
    __shared__ __align__(16) float Ws[K * 64];
    for (int i = threadIdx.x; i < K * 64; i += 128) Ws[i] = Wg[i];
    __syncthreads();
    int colh = threadIdx.x & 1;          // cols [colh*32, colh*32+32)
    int rowp = threadIdx.x >> 1;         // 0..63
    int r0 = lb * 128 + rowp * 2;
    if (r0 >= n) return;
    int nr = n - r0; if (nr > 2) nr = 2;
    bool vb = (nr == 2);

    double acc[2][16];
#pragma unroll
    for (int r = 0; r < 2; r++)
#pragma unroll
        for (int j = 0; j < 16; j++) acc[r][j] = 0.0;

    const float4* a4 = reinterpret_cast<const float4*>(A + (size_t)r0 * K);
    const float4* b4 = reinterpret_cast<const float4*>(A + (size_t)(r0 + 1) * K);
#pragma unroll 1
    for (int k4 = 0; k4 < K / 4; k4++) {
        float4 av = a4[k4];
        float4 bv = vb ? b4[k4] : make_float4(0.f, 0.f, 0.f, 0.f);
        float aa[4] = {av.x, av.y, av.z, av.w};
        float bb[4] = {bv.x, bv.y, bv.z, bv.w};
#pragma unroll
        for (int kk = 0; kk < 4; kk++) {
            const double2* w2p = reinterpret_cast<const double2*>(
                &Ws[(k4 * 4 + kk) * 64 + colh * 32]);
            double2 w2[8];
#pragma unroll
            for (int j = 0; j < 8; j++) w2[j] = w2p[j];   // 8x LDS.128
            double ap, bp;
            asm("mov.b64 %0, {%1,%1};" : "=d"(ap) : "f"(aa[kk]));
            asm("mov.b64 %0, {%1,%1};" : "=d"(bp) : "f"(bb[kk]));
#pragma unroll
            for (int j = 0; j < 8; j++) {
                asm("fma.rn.f32x2 %0, %1, %2, %0;" : "+d"(acc[0][2*j])   : "d"(w2[j].x), "d"(ap));
                asm("fma.rn.f32x2 %0, %1, %2, %0;" : "+d"(acc[0][2*j+1]) : "d"(w2[j].y), "d"(ap));
                asm("fma.rn.f32x2 %0, %1, %2, %0;" : "+d"(acc[1][2*j])   : "d"(w2[j].x), "d"(bp));
                asm("fma.rn.f32x2 %0, %1, %2, %0;" : "+d"(acc[1][2*j+1]) : "d"(w2[j].y), "d"(bp));
            }
        }
    }
#pragma unroll
    for (int r = 0; r < 2; r++) {
        if (r >= nr) break;
        __half2 t[16];
#pragma unroll
        for (int j = 0; j < 16; j++) {
            float lo, hi;
            asm("mov.b64 {%0,%1}, %2;" : "=f"(lo), "=f"(hi) : "d"(acc[r][j]));
            t[j] = __floats2half2_rn(lo, hi);
        }
        uint4* o = reinterpret_cast<uint4*>(outH + (size_t)(r0 + r) * 32 + colh * 16);
        const uint4* ts = reinterpret_cast<const uint4*>(t);
#pragma unroll
        for (int i = 0; i < 4; i++) o[i] = ts[i];
    }
}

template<int K>
__global__ void __launch_bounds__(128, 3) gemm_all(const float* __restrict__ A1,
                                                   const float* __restrict__ W1,
                                                   __half2* __restrict__ o1,
                                                   const float* __restrict__ A2,
                                                   const float* __restrict__ W2,
                                                   __half2* __restrict__ o2) {
    int gb = blockIdx.x;
    if (gb < GB1) gemm_body<K>(A1, W1, o1, N1V, gb);
    else          gemm_body<K>(A2, W2, o2, N2V, gb - GB1);
}

// ---------------- fused gather: relu(sum nrm*h[src] + h/deg + bias); fp16 in, fp32 acc ----
template<bool POOL>
__global__ void gather_all(const __half2* __restrict__ h1, const float* __restrict__ bias1,
                           float* __restrict__ out1,
                           const __half2* __restrict__ h2g, const float* __restrict__ bias2,
                           float* __restrict__ out2,
                           const int* __restrict__ roi1, const int* __restrict__ bat1,
                           const int* __restrict__ roi2, const int* __restrict__ bat2) {
    int w = (blockIdx.x * blockDim.x + threadIdx.x) >> 5;
    int lane = threadIdx.x & 31;
    const EP* pay; const int* rowptr; const __half2* hh; const float* dinv; const float* bias;
    float* out; const int* roi; const int* bat; float* pool; float* cntf;
    int node;
    if (w < N1V) {
        node = w; pay = g_pay1; rowptr = g_rowptr1; hh = h1; dinv = g_deg1; bias = bias1;
        out = out1; roi = roi1; bat = bat1; pool = g_pool1; cntf = g_cntf1;
    } else if (w < N1V + N2V) {
        node = w - N1V; pay = g_pay2; rowptr = g_rowptr2; hh = h2g; dinv = g_deg2; bias = bias2;
        out = out2; roi = roi2; bat = bat2; pool = g_pool2; cntf = g_cntf2;
    } else return;

    int beg = rowptr[node], end = rowptr[node + 1];
    float di = dinv[node];
    float sl = di * di;
    float2 hv = __half22float2(hh[(size_t)node * 32 + lane]);
    float ax = hv.x * sl, ay = hv.y * sl;

    int e = beg;
    for (; e + 8 <= end; e += 8) {
        EP p[8];
#pragma unroll
        for (int i = 0; i < 8; i++) p[i] = pay[e + i];
        float2 v[8];
#pragma unroll
        for (int i = 0; i < 8; i++) v[i] = __half22float2(hh[(size_t)p[i].s * 32 + lane]);
#pragma unroll
        for (int i = 0; i < 8; i++) { ax += v[i].x * p[i].w; ay += v[i].y * p[i].w; }
    }
    for (; e < end; e++) {
        EP p = pay[e];
        float2 v = __half22float2(hh[(size_t)p.s * 32 + lane]);
        ax += v.x * p.w;
        ay += v.y * p.w;
    }
    float2 b2 = reinterpret_cast<const float2*>(bias)[lane];
    ax = fmaxf(ax + b2.x, 0.0f);
    ay = fmaxf(ay + b2.y, 0.0f);
    if (POOL) {
        int seg = bat[node] * ROIS + roi[node];
        float* p = pool + (size_t)seg * 64 + lane * 2;
        asm volatile("red.global.add.v2.f32 [%0], {%1,%2};"
                     :: "l"(p), "f"(ax), "f"(ay) : "memory");
        if (lane == 0) atomicAdd(&cntf[seg], 1.0f);
    } else {
        reinterpret_cast<float2*>(out)[(size_t)node * 32 + lane] = make_float2(ax, ay);
    }
}

// ---------------- pooling means + embeddings -> d_out ----------------
__global__ void pool_finalize(float* __restrict__ out) {
    int idx = blockIdx.x * 256 + threadIdx.x;
    if (idx >= NSEG * 64) return;
    int seg = idx >> 6;
    float e1 = g_pool1[idx] / fmaxf(g_cntf1[seg], 1.0f);
    float e2 = g_pool2[idx] / fmaxf(g_cntf2[seg], 1.0f);
    float sv = e1 + e2;
    out[32 + idx] = e1;
    out[32 + BSZV * EMBV + idx] = e2;
    out[32 + 2 * BSZV * EMBV + idx] = sv;
    g_s[idx] = sv;
}

// ---------------- classifier ----------------
__global__ void mlp1_partial(const float* __restrict__ Wm1) {
    __shared__ float sm[BSZV * KSLICE];   // 9.5 KB
    int ks = blockIdx.y;
    int k0 = ks * KSLICE;
    for (int i = threadIdx.x; i < BSZV * KSLICE; i += blockDim.x) {
        int b = i / KSLICE, kk = i - b * KSLICE;
        sm[i] = g_s[b * EMBV + k0 + kk];
    }
    __syncthreads();
    int j = blockIdx.x * 128 + threadIdx.x;
    if (j >= 1000) return;
    float acc[BSZV];
#pragma unroll
    for (int b = 0; b < BSZV; b++) acc[b] = 0.0f;
#pragma unroll 1
    for (int kk = 0; kk < KSLICE; kk += 4) {
        float w0 = Wm1[(size_t)(k0 + kk) * 1000 + j];
        float w1 = Wm1[(size_t)(k0 + kk + 1) * 1000 + j];
        float w2 = Wm1[(size_t)(k0 + kk + 2) * 1000 + j];
        float w3 = Wm1[(size_t)(k0 + kk + 3) * 1000 + j];
#pragma unroll
        for (int b = 0; b < BSZV; b++) {
            float4 sv = *reinterpret_cast<const float4*>(&sm[b * KSLICE + kk]);
            acc[b] += sv.x * w0 + sv.y * w1 + sv.z * w2 + sv.w * w3;
        }
    }
#pragma unroll
    for (int b = 0; b < BSZV; b++) g_part[((size_t)ks * BSZV + b) * 1000 + j] = acc[b];
}

__global__ void mlp1_reduce(const float* __restrict__ bm1, const float* __restrict__ gamma,
                            const float* __restrict__ beta, const float* __restrict__ mean,
                            const float* __restrict__ var) {
    int idx = blockIdx.x * 256 + threadIdx.x;
    if (idx >= BSZV * 1000) return;
    int b = idx / 1000, j = idx - b * 1000;
    float v = bm1[j];
#pragma unroll 8
    for (int ks = 0; ks < NKS; ks++) v += g_part[((size_t)ks * BSZV + b) * 1000 + j];
    float sc = gamma[j] * rsqrtf(var[j] + BN_EPSV);
    v = (v - mean[j]) * sc + beta[j];
    g_hidden[idx] = v > 0.0f ? v : LRELU * v;
}

__global__ void mlp2_kernel(const float* __restrict__ Wm2, const float* __restrict__ bm2,
                            float* __restrict__ out) {
    int w = threadIdx.x >> 5, lane = threadIdx.x & 31;
    int b = w >> 1, o = w & 1;
    float acc = 0.0f;
    for (int k = lane; k < 1000; k += 32) acc += g_hidden[b * 1000 + k] * Wm2[k * 2 + o];
#pragma unroll
    for (int off = 16; off; off >>= 1) acc += __shfl_down_sync(0xffffffffu, acc, off);
    if (lane == 0) out[b * 2 + o] = acc + bm2[o];
}

// ---------------- launcher ----------------
extern "C" void kernel_launch(void* const* d_in, const int* in_sizes, int n_in,
                              void* d_out, int out_size) {
    const float* x1   = (const float*)d_in[0];
    const int*   nlab = (const int*)  d_in[1];
    const int*   ei1  = (const int*)  d_in[2];
    const float* ew1  = (const float*)d_in[3];
    const int*   bat1 = (const int*)  d_in[4];
    const float* x2   = (const float*)d_in[5];
    const int*   rlab = (const int*)  d_in[6];
    const int*   ei2  = (const int*)  d_in[7];
    const float* ew2  = (const float*)d_in[8];
    const int*   bat2 = (const int*)  d_in[9];
    const float* W1a = (const float*)d_in[10]; const float* b1a = (const float*)d_in[11];
    const float* W1b = (const float*)d_in[12]; const float* b1b = (const float*)d_in[13];
    const float* W2a = (const float*)d_in[14]; const float* b2a = (const float*)d_in[15];
    const float* W2b = (const float*)d_in[16]; const float* b2b = (const float*)d_in[17];
    const float* Wm1 = (const float*)d_in[18]; const float* bm1 = (const float*)d_in[19];
    const float* gam = (const float*)d_in[20]; const float* bet = (const float*)d_in[21];
    const float* bmn = (const float*)d_in[22]; const float* bvr = (const float*)d_in[23];
    const float* Wm2 = (const float*)d_in[24]; const float* bm2 = (const float*)d_in[25];

    const int* src1 = ei1;          const int* dst1 = ei1 + E1V;
    const int* src2 = ei2;          const int* dst2 = ei2 + E2V;

    __half2 *bufH1, *bufH2;
    float *bufY1, *bufY2;
    cudaGetSymbolAddress((void**)&bufH1, g_bufH1);
    cudaGetSymbolAddress((void**)&bufY1, g_bufY1);
    cudaGetSymbolAddress((void**)&bufH2, g_bufH2);
    cudaGetSymbolAddress((void**)&bufY2, g_bufY2);

    float* out = (float*)d_out;
    auto cdiv = [](long long a, long long b) { return (int)((a + b - 1) / b); };

    // structure build + layer-A GEMM (gemm kept 4th: ncu samples launch #4)
    init_kernel<<<cdiv(NSEG * 64, 256), 256>>>();
    hist_all<<<cdiv(E1V + E2V, 256), 256>>>(dst1, ew1, dst2, ew2);
    rsqrt_all<<<cdiv(N1V + N2V, 256), 256>>>();
    gemm_all<128><<<GB1 + GB2, 128>>>(x1, W1a, bufH1, x2, W2a, bufH2);
    scan_block_all<<<NB1 + NB2, 256>>>();
    scan_bsum_all<<<2, 512>>>();
    scan_add_all<<<NB1 + NB2, 256>>>();
    csr_all<<<cdiv(E1V + E2V, 256), 256>>>(src1, dst1, ew1, src2, dst2, ew2);
    // layer-A aggregate + bias + relu (fp32 out for gemmB)
    gather_all<false><<<cdiv((long long)(N1V + N2V) * 32, 256), 256>>>(
        bufH1, b1a, bufY1, bufH2, b2a, bufY2, nullptr, nullptr, nullptr, nullptr);
    // layer-B GEMM (fp32 in, fp16 out)
    gemm_all<64><<<GB1 + GB2, 128>>>(bufY1, W1b, bufH1, bufY2, W2b, bufH2);
    // layer-B aggregate + bias + relu + ROI pooling
    gather_all<true><<<cdiv((long long)(N1V + N2V) * 32, 256), 256>>>(
        bufH1, b1b, nullptr, bufH2, b2b, nullptr, nlab, bat1, rlab, bat2);
    // pooled means + embeddings -> d_out
    pool_finalize<<<cdiv(NSEG * 64, 256), 256>>>(out);
    // classifier
    mlp1_partial<<<dim3(8, NKS), 128>>>(Wm1);
    mlp1_reduce<<<cdiv(BSZV * 1000, 256), 256>>>(bm1, gam, bet, bmn, bvr);
    mlp2_kernel<<<1, 1024>>>(Wm2, bm2, out);
}

// round 7
// speedup vs baseline: 1.3032x; 1.2466x over previous
#include <cuda_runtime.h>
#include <cuda_fp16.h>

// ---------------- problem constants ----------------
#define N1V   131072
#define N2V   2368
#define E1V   2097152
#define E2V   37888
#define ROIS  148
#define BSZV  16
#define HIDV  64
#define EMBV  (ROIS * HIDV)      // 9472
#define NSEG  (BSZV * ROIS)      // 2368
#define NKS   64
#define KSLICE 148               // 9472 / 64
#define BN_EPSV 1e-5f
#define LRELU  0.01f

#define NB1 512                  // N1V / 256
#define NB2 10                   // ceil(N2V / 256)
#define GB1T 1024                // tc-gemm blocks graph1 (128 rows each)
#define GB2T 19                  // ceil(N2V / 128)

struct __align__(8) EP { int s; float w; };

// ---------------- scratch (device globals; no runtime alloc) ----------------
__device__ __align__(16) __half2 g_bufH1[(size_t)N1V * 32];   // gemm out / gather in (fp16)
__device__ __align__(16) __half2 g_bufG1[(size_t)N1V * 32];   // gatherA out (fp16) = gemmB A
__device__ float g_deg1[N1V];
__device__ int   g_cnti1[N1V];
__device__ int   g_rowptr1[N1V + 1];
__device__ int   g_cursor1[N1V];
__device__ int   g_bsum1[512];
__device__ EP    g_pay1[E1V];

__device__ __align__(16) __half2 g_bufH2[(size_t)N2V * 32];
__device__ __align__(16) __half2 g_bufG2[(size_t)N2V * 32];
__device__ float g_deg2[N2V];
__device__ int   g_cnti2[N2V];
__device__ int   g_rowptr2[N2V + 1];
__device__ int   g_cursor2[N2V];
__device__ int   g_bsum2[512];
__device__ EP    g_pay2[E2V];

__device__ __align__(16) float g_pool1[NSEG * 64];
__device__ float g_cntf1[NSEG];
__device__ __align__(16) float g_pool2[NSEG * 64];
__device__ float g_cntf2[NSEG];

__device__ __align__(16) float g_s[BSZV * EMBV];
__device__ float g_part[NKS * BSZV * 1000];
__device__ float g_hidden[BSZV * 1000];

// ---------------- setup kernels ----------------
__global__ void init_kernel() {
    int idx = blockIdx.x * 256 + threadIdx.x;
    if (idx < N1V) { g_deg1[idx] = 1.0f; g_cnti1[idx] = 0; }
    if (idx < N2V) { g_deg2[idx] = 1.0f; g_cnti2[idx] = 0; }
    if (idx < NSEG * 64) { g_pool1[idx] = 0.0f; g_pool2[idx] = 0.0f; }
    if (idx < NSEG)      { g_cntf1[idx] = 0.0f; g_cntf2[idx] = 0.0f; }
}

__global__ void hist_all(const int* __restrict__ dst1, const float* __restrict__ ew1,
                         const int* __restrict__ dst2, const float* __restrict__ ew2) {
    int e = blockIdx.x * 256 + threadIdx.x;
    if (e < E1V) {
        int d = dst1[e];
        atomicAdd(&g_cnti1[d], 1);
        atomicAdd(&g_deg1[d], ew1[e]);
    } else if (e < E1V + E2V) {
        int e2 = e - E1V;
        int d = dst2[e2];
        atomicAdd(&g_cnti2[d], 1);
        atomicAdd(&g_deg2[d], ew2[e2]);
    }
}

__global__ void rsqrt_all() {
    int i = blockIdx.x * 256 + threadIdx.x;
    if (i < N1V) g_deg1[i] = rsqrtf(g_deg1[i]);
    else if (i < N1V + N2V) g_deg2[i - N1V] = rsqrtf(g_deg2[i - N1V]);
}

__global__ void scan_block_all() {
    __shared__ int sm[256];
    int gb = blockIdx.x;
    const int* cnt; int* excl; int* bsum; int n; int lb;
    if (gb < NB1) { cnt = g_cnti1; excl = g_rowptr1; bsum = g_bsum1; n = N1V; lb = gb; }
    else          { cnt = g_cnti2; excl = g_rowptr2; bsum = g_bsum2; n = N2V; lb = gb - NB1; }
    int i = lb * 256 + threadIdx.x;
    int v = (i < n) ? cnt[i] : 0;
    sm[threadIdx.x] = v; __syncthreads();
#pragma unroll
    for (int off = 1; off < 256; off <<= 1) {
        int t = (threadIdx.x >= off) ? sm[threadIdx.x - off] : 0;
        __syncthreads();
        sm[threadIdx.x] += t;
        __syncthreads();
    }
    if (i < n) excl[i] = sm[threadIdx.x] - v;
    if (threadIdx.x == 255) bsum[lb] = sm[255];
}

__global__ void scan_bsum_all() {
    __shared__ int sm[512];
    int* bsum = (blockIdx.x == 0) ? g_bsum1 : g_bsum2;
    int nb    = (blockIdx.x == 0) ? NB1 : NB2;
    int v = (threadIdx.x < nb) ? bsum[threadIdx.x] : 0;
    sm[threadIdx.x] = v; __syncthreads();
#pragma unroll
    for (int off = 1; off < 512; off <<= 1) {
        int t = (threadIdx.x >= off) ? sm[threadIdx.x - off] : 0;
        __syncthreads();
        sm[threadIdx.x] += t;
        __syncthreads();
    }
    if (threadIdx.x < nb) bsum[threadIdx.x] = sm[threadIdx.x] - v;
}

__global__ void scan_add_all() {
    int gb = blockIdx.x;
    int* rowptr; int* cursor; const int* bsum; int n; int E; int lb;
    if (gb < NB1) { rowptr = g_rowptr1; cursor = g_cursor1; bsum = g_bsum1; n = N1V; E = E1V; lb = gb; }
    else          { rowptr = g_rowptr2; cursor = g_cursor2; bsum = g_bsum2; n = N2V; E = E2V; lb = gb - NB1; }
    int i = lb * 256 + threadIdx.x;
    if (i < n) {
        int r = rowptr[i] + bsum[i >> 8];
        rowptr[i] = r;
        cursor[i] = r;
    }
    if (i == 0) rowptr[n] = E;
}

__global__ void csr_all(const int* __restrict__ src1, const int* __restrict__ dst1,
                        const float* __restrict__ ew1,
                        const int* __restrict__ src2, const int* __restrict__ dst2,
                        const float* __restrict__ ew2) {
    int e = blockIdx.x * 256 + threadIdx.x;
    if (e < E1V) {
        int s = src1[e], d = dst1[e];
        EP p; p.s = s; p.w = g_deg1[s] * ew1[e] * g_deg1[d];
        int pos = atomicAdd(&g_cursor1[d], 1);
        g_pay1[pos] = p;
    } else if (e < E1V + E2V) {
        int e2 = e - E1V;
        int s = src2[e2], d = dst2[e2];
        EP p; p.s = s; p.w = g_deg2[s] * ew2[e2] * g_deg2[d];
        int pos = atomicAdd(&g_cursor2[d], 1);
        g_pay2[pos] = p;
    }
}

// ---------------- tensor-core GEMM: outH(n,64 fp16) = A(n,K) @ W(K,64 fp32) ----
// mma.sync.m16n8k16.row.col f16*f16+f32. Warp tile = 16 rows x 64 cols.
// Block = 256 thr = 8 warps = 128 rows. W transposed to fp16 smem, +8 pad
// (bank = 4g+t per lane -> conflict-free). A frags loaded straight from gmem.
template<int K, bool AF32>
__device__ __forceinline__ void gemm_tc_body(const void* Av, const float* __restrict__ Wg,
                                             __half2* __restrict__ outH, int n, int lb) {
    constexpr int KS = K + 8;
    __shared__ __half Wt[64 * KS];
    for (int i = threadIdx.x; i < K * 64; i += 256) {
        int k = i >> 6, nn = i & 63;
        Wt[nn * KS + k] = __float2half(Wg[i]);
    }
    __syncthreads();
    int warp = threadIdx.x >> 5, lane = threadIdx.x & 31;
    int g = lane >> 2, t = lane & 3;
    int rowBase = lb * 128 + warp * 16;
    if (rowBase >= n) return;
    int rA = rowBase + g;     if (rA >= n) rA = n - 1;
    int rB = rowBase + g + 8; if (rB >= n) rB = n - 1;

    float acc[8][4];
#pragma unroll
    for (int nt = 0; nt < 8; nt++)
#pragma unroll
        for (int j = 0; j < 4; j++) acc[nt][j] = 0.0f;

    const float*  fA = AF32 ? (const float*)Av  + (size_t)rA * K + 2 * t : nullptr;
    const float*  fB = AF32 ? (const float*)Av  + (size_t)rB * K + 2 * t : nullptr;
    const __half* hA = AF32 ? nullptr : (const __half*)Av + (size_t)rA * K + 2 * t;
    const __half* hB = AF32 ? nullptr : (const __half*)Av + (size_t)rB * K + 2 * t;

#pragma unroll
    for (int kt = 0; kt < K / 16; kt++) {
        unsigned a0, a1, a2, a3;
        if (AF32) {
            float2 v0 = *(const float2*)(fA + kt * 16);
            float2 v1 = *(const float2*)(fB + kt * 16);
            float2 v2 = *(const float2*)(fA + kt * 16 + 8);
            float2 v3 = *(const float2*)(fB + kt * 16 + 8);
            asm("cvt.rn.f16x2.f32 %0, %1, %2;" : "=r"(a0) : "f"(v0.y), "f"(v0.x));
            asm("cvt.rn.f16x2.f32 %0, %1, %2;" : "=r"(a1) : "f"(v1.y), "f"(v1.x));
            asm("cvt.rn.f16x2.f32 %0, %1, %2;" : "=r"(a2) : "f"(v2.y), "f"(v2.x));
            asm("cvt.rn.f16x2.f32 %0, %1, %2;" : "=r"(a3) : "f"(v3.y), "f"(v3.x));
        } else {
            a0 = *(const unsigned*)(hA + kt * 16);
            a1 = *(const unsigned*)(hB + kt * 16);
            a2 = *(const unsigned*)(hA + kt * 16 + 8);
            a3 = *(const unsigned*)(hB + kt * 16 + 8);
        }
#pragma unroll
        for (int nt = 0; nt < 8; nt++) {
            const __half* wp = &Wt[(nt * 8 + g) * KS + kt * 16 + 2 * t];
            unsigned b0 = *(const unsigned*)wp;
            unsigned b1 = *(const unsigned*)(wp + 8);
            asm volatile(
                "mma.sync.aligned.m16n8k16.row.col.f32.f16.f16.f32 "
                "{%0,%1,%2,%3}, {%4,%5,%6,%7}, {%8,%9}, {%0,%1,%2,%3};"
                : "+f"(acc[nt][0]), "+f"(acc[nt][1]), "+f"(acc[nt][2]), "+f"(acc[nt][3])
                : "r"(a0), "r"(a1), "r"(a2), "r"(a3), "r"(b0), "r"(b1));
        }
    }
    bool okA = (rowBase + g) < n;
    bool okB = (rowBase + g + 8) < n;
#pragma unroll
    for (int nt = 0; nt < 8; nt++) {
        if (okA) outH[(size_t)(rowBase + g) * 32 + nt * 4 + t] =
            __floats2half2_rn(acc[nt][0], acc[nt][1]);
        if (okB) outH[(size_t)(rowBase + g + 8) * 32 + nt * 4 + t] =
            __floats2half2_rn(acc[nt][2], acc[nt][3]);
    }
}

template<int K, bool AF32>
__global__ void __launch_bounds__(256, 2) gemm_tc(const void* A1, const float* __restrict__ W1,
                                                  __half2* __restrict__ o1,
                                                  const void* A2, const float* __restrict__ W2,
                                                  __half2* __restrict__ o2) {
    int gb = blockIdx.x;
    if (gb < GB1T) gemm_tc_body<K, AF32>(A1, W1, o1, N1V, gb);
    else           gemm_tc_body<K, AF32>(A2, W2, o2, N2V, gb - GB1T);
}

// ---------------- fused gather: relu(sum nrm*h[src] + h/deg + bias); fp16 in, fp32 acc ----
template<bool POOL>
__global__ void gather_all(const __half2* __restrict__ h1, const float* __restrict__ bias1,
                           __half2* __restrict__ out1,
                           const __half2* __restrict__ h2g, const float* __restrict__ bias2,
                           __half2* __restrict__ out2,
                           const int* __restrict__ roi1, const int* __restrict__ bat1,
                           const int* __restrict__ roi2, const int* __restrict__ bat2) {
    int w = (blockIdx.x * blockDim.x + threadIdx.x) >> 5;
    int lane = threadIdx.x & 31;
    const EP* pay; const int* rowptr; const __half2* hh; const float* dinv; const float* bias;
    __half2* out; const int* roi; const int* bat; float* pool; float* cntf;
    int node;
    if (w < N1V) {
        node = w; pay = g_pay1; rowptr = g_rowptr1; hh = h1; dinv = g_deg1; bias = bias1;
        out = out1; roi = roi1; bat = bat1; pool = g_pool1; cntf = g_cntf1;
    } else if (w < N1V + N2V) {
        node = w - N1V; pay = g_pay2; rowptr = g_rowptr2; hh = h2g; dinv = g_deg2; bias = bias2;
        out = out2; roi = roi2; bat = bat2; pool = g_pool2; cntf = g_cntf2;
    } else return;

    int beg = rowptr[node], end = rowptr[node + 1];
    float di = dinv[node];
    float sl = di * di;
    float2 hv = __half22float2(hh[(size_t)node * 32 + lane]);
    float ax = hv.x * sl, ay = hv.y * sl;

    int e = beg;
    for (; e + 8 <= end; e += 8) {
        EP p[8];
#pragma unroll
        for (int i = 0; i < 8; i++) p[i] = pay[e + i];
        float2 v[8];
#pragma unroll
        for (int i = 0; i < 8; i++) v[i] = __half22float2(hh[(size_t)p[i].s * 32 + lane]);
#pragma unroll
        for (int i = 0; i < 8; i++) { ax += v[i].x * p[i].w; ay += v[i].y * p[i].w; }
    }
    for (; e < end; e++) {
        EP p = pay[e];
        float2 v = __half22float2(hh[(size_t)p.s * 32 + lane]);
        ax += v.x * p.w;
        ay += v.y * p.w;
    }
    float2 b2 = reinterpret_cast<const float2*>(bias)[lane];
    ax = fmaxf(ax + b2.x, 0.0f);
    ay = fmaxf(ay + b2.y, 0.0f);
    if (POOL) {
        int seg = bat[node] * ROIS + roi[node];
        float* p = pool + (size_t)seg * 64 + lane * 2;
        asm volatile("red.global.add.v2.f32 [%0], {%1,%2};"
                     :: "l"(p), "f"(ax), "f"(ay) : "memory");
        if (lane == 0) atomicAdd(&cntf[seg], 1.0f);
    } else {
        out[(size_t)node * 32 + lane] = __floats2half2_rn(ax, ay);
    }
}

// ---------------- pooling means + embeddings -> d_out ----------------
__global__ void pool_finalize(float* __restrict__ out) {
    int idx = blockIdx.x * 256 + threadIdx.x;
    if (idx >= NSEG * 64) return;
    int seg = idx >> 6;
    float e1 = g_pool1[idx] / fmaxf(g_cntf1[seg], 1.0f);
    float e2 = g_pool2[idx] / fmaxf(g_cntf2[seg], 1.0f);
    float sv = e1 + e2;
    out[32 + idx] = e1;
    out[32 + BSZV * EMBV + idx] = e2;
    out[32 + 2 * BSZV * EMBV + idx] = sv;
    g_s[idx] = sv;
}

// ---------------- classifier ----------------
__global__ void mlp1_partial(const float* __restrict__ Wm1) {
    __shared__ float sm[BSZV * KSLICE];   // 9.5 KB
    int ks = blockIdx.y;
    int k0 = ks * KSLICE;
    for (int i = threadIdx.x; i < BSZV * KSLICE; i += blockDim.x) {
        int b = i / KSLICE, kk = i - b * KSLICE;
        sm[i] = g_s[b * EMBV + k0 + kk];
    }
    __syncthreads();
    int j = blockIdx.x * 128 + threadIdx.x;
    if (j >= 1000) return;
    float acc[BSZV];
#pragma unroll
    for (int b = 0; b < BSZV; b++) acc[b] = 0.0f;
#pragma unroll 1
    for (int kk = 0; kk < KSLICE; kk += 4) {
        float w0 = Wm1[(size_t)(k0 + kk) * 1000 + j];
        float w1 = Wm1[(size_t)(k0 + kk + 1) * 1000 + j];
        float w2 = Wm1[(size_t)(k0 + kk + 2) * 1000 + j];
        float w3 = Wm1[(size_t)(k0 + kk + 3) * 1000 + j];
#pragma unroll
        for (int b = 0; b < BSZV; b++) {
            float4 sv = *reinterpret_cast<const float4*>(&sm[b * KSLICE + kk]);
            acc[b] += sv.x * w0 + sv.y * w1 + sv.z * w2 + sv.w * w3;
        }
    }
#pragma unroll
    for (int b = 0; b < BSZV; b++) g_part[((size_t)ks * BSZV + b) * 1000 + j] = acc[b];
}

__global__ void mlp1_reduce(const float* __restrict__ bm1, const float* __restrict__ gamma,
                            const float* __restrict__ beta, const float* __restrict__ mean,
                            const float* __restrict__ var) {
    int idx = blockIdx.x * 256 + threadIdx.x;
    if (idx >= BSZV * 1000) return;
    int b = idx / 1000, j = idx - b * 1000;
    float v = bm1[j];
#pragma unroll 8
    for (int ks = 0; ks < NKS; ks++) v += g_part[((size_t)ks * BSZV + b) * 1000 + j];
    float sc = gamma[j] * rsqrtf(var[j] + BN_EPSV);
    v = (v - mean[j]) * sc + beta[j];
    g_hidden[idx] = v > 0.0f ? v : LRELU * v;
}

__global__ void mlp2_kernel(const float* __restrict__ Wm2, const float* __restrict__ bm2,
                            float* __restrict__ out) {
    int w = threadIdx.x >> 5, lane = threadIdx.x & 31;
    int b = w >> 1, o = w & 1;
    float acc = 0.0f;
    for (int k = lane; k < 1000; k += 32) acc += g_hidden[b * 1000 + k] * Wm2[k * 2 + o];
#pragma unroll
    for (int off = 16; off; off >>= 1) acc += __shfl_down_sync(0xffffffffu, acc, off);
    if (lane == 0) out[b * 2 + o] = acc + bm2[o];
}

// ---------------- launcher ----------------
extern "C" void kernel_launch(void* const* d_in, const int* in_sizes, int n_in,
                              void* d_out, int out_size) {
    const float* x1   = (const float*)d_in[0];
    const int*   nlab = (const int*)  d_in[1];
    const int*   ei1  = (const int*)  d_in[2];
    const float* ew1  = (const float*)d_in[3];
    const int*   bat1 = (const int*)  d_in[4];
    const float* x2   = (const float*)d_in[5];
    const int*   rlab = (const int*)  d_in[6];
    const int*   ei2  = (const int*)  d_in[7];
    const float* ew2  = (const float*)d_in[8];
    const int*   bat2 = (const int*)  d_in[9];
    const float* W1a = (const float*)d_in[10]; const float* b1a = (const float*)d_in[11];
    const float* W1b = (const float*)d_in[12]; const float* b1b = (const float*)d_in[13];
    const float* W2a = (const float*)d_in[14]; const float* b2a = (const float*)d_in[15];
    const float* W2b = (const float*)d_in[16]; const float* b2b = (const float*)d_in[17];
    const float* Wm1 = (const float*)d_in[18]; const float* bm1 = (const float*)d_in[19];
    const float* gam = (const float*)d_in[20]; const float* bet = (const float*)d_in[21];
    const float* bmn = (const float*)d_in[22]; const float* bvr = (const float*)d_in[23];
    const float* Wm2 = (const float*)d_in[24]; const float* bm2 = (const float*)d_in[25];

    const int* src1 = ei1;          const int* dst1 = ei1 + E1V;
    const int* src2 = ei2;          const int* dst2 = ei2 + E2V;

    __half2 *bufH1, *bufH2, *bufG1, *bufG2;
    cudaGetSymbolAddress((void**)&bufH1, g_bufH1);
    cudaGetSymbolAddress((void**)&bufG1, g_bufG1);
    cudaGetSymbolAddress((void**)&bufH2, g_bufH2);
    cudaGetSymbolAddress((void**)&bufG2, g_bufG2);

    float* out = (float*)d_out;
    auto cdiv = [](long long a, long long b) { return (int)((a + b - 1) / b); };

    // structure build + layer-A GEMM (gemm kept 4th: ncu samples launch #4)
    init_kernel<<<cdiv(NSEG * 64, 256), 256>>>();
    hist_all<<<cdiv(E1V + E2V, 256), 256>>>(dst1, ew1, dst2, ew2);
    rsqrt_all<<<cdiv(N1V + N2V, 256), 256>>>();
    gemm_tc<128, true><<<GB1T + GB2T, 256>>>(x1, W1a, bufH1, x2, W2a, bufH2);
    scan_block_all<<<NB1 + NB2, 256>>>();
    scan_bsum_all<<<2, 512>>>();
    scan_add_all<<<NB1 + NB2, 256>>>();
    csr_all<<<cdiv(E1V + E2V, 256), 256>>>(src1, dst1, ew1, src2, dst2, ew2);
    // layer-A aggregate + bias + relu -> fp16 (gemmB input)
    gather_all<false><<<cdiv((long long)(N1V + N2V) * 32, 256), 256>>>(
        bufH1, b1a, bufG1, bufH2, b2a, bufG2, nullptr, nullptr, nullptr, nullptr);
    // layer-B GEMM (fp16 in, fp16 out)
    gemm_tc<64, false><<<GB1T + GB2T, 256>>>(bufG1, W1b, bufH1, bufG2, W2b, bufH2);
    // layer-B aggregate + bias + relu + ROI pooling
    gather_all<true><<<cdiv((long long)(N1V + N2V) * 32, 256), 256>>>(
        bufH1, b1b, nullptr, bufH2, b2b, nullptr, nlab, bat1, rlab, bat2);
    // pooled means + embeddings -> d_out
    pool_finalize<<<cdiv(NSEG * 64, 256), 256>>>(out);
    // classifier
    mlp1_partial<<<dim3(8, NKS), 128>>>(Wm1);
    mlp1_reduce<<<cdiv(BSZV * 1000, 256), 256>>>(bm1, gam, bet, bmn, bvr);
    mlp2_kernel<<<1, 1024>>>(Wm2, bm2, out);
}